// round 7
// baseline (speedup 1.0000x reference)
#include <cuda_runtime.h>
#include <cuda_bf16.h>

#define N_NODES  100000
#define N_EDGES  1600000
#define N_GRAPHS 2048
#define HID      64
#define IN_F     14
#define N_CLS    2
#define BN_EPS   1e-5f

// ---------------- scratch (static __device__: allocation-free) ----------------
__device__ float g_dinv [N_NODES];          // deg accum -> dinv
__device__ float g_dinv2[N_NODES];          // 1/deg  (self-loop coeff)
__device__ int   g_erow [N_EDGES];
__device__ int   g_ecol [N_EDGES];
__device__ float g_norm [N_EDGES];
__device__ float g_xw   [N_NODES * HID];    // x @ W  (gather source)
__device__ float g_accA [N_NODES * HID];    // ping
__device__ float g_accB [N_NODES * HID];    // pong
__device__ float g_stats[128];              // [0:64) sum, [64:128) sumsq
__device__ float g_scale[HID];
__device__ float g_shift[HID];

// ---------------- helpers ----------------
__device__ __forceinline__ void red_add4(float* p, float4 v) {
    asm volatile("red.global.add.v4.f32 [%0], {%1,%2,%3,%4};"
                 :: "l"(p), "f"(v.x), "f"(v.y), "f"(v.z), "f"(v.w) : "memory");
}

__global__ void zero4(float4* __restrict__ p, int n4) {
    int i = blockIdx.x * blockDim.x + threadIdx.x;
    int stride = gridDim.x * blockDim.x;
    float4 z = make_float4(0.f, 0.f, 0.f, 0.f);
    for (; i < n4; i += stride) p[i] = z;
}

// ---------------- edge prep (indices are int32!) ----------------
__global__ void deg_kernel(const int* __restrict__ ei, const float* __restrict__ w) {
    int e = blockIdx.x * blockDim.x + threadIdx.x;   // grid exact: 1.6M/256
    int col = ei[N_EDGES + e];
    if ((unsigned)col < (unsigned)N_NODES)
        atomicAdd(&g_dinv[col], w[e]);
}

__global__ void dinv_kernel() {
    int i = blockIdx.x * blockDim.x + threadIdx.x;
    if (i >= N_NODES) return;
    float d = g_dinv[i] + 1.0f;                      // +1 self loop
    g_dinv[i]  = rsqrtf(d);
    g_dinv2[i] = 1.0f / d;
}

__global__ void prep_kernel(const int* __restrict__ ei, const float* __restrict__ w) {
    int e = blockIdx.x * blockDim.x + threadIdx.x;   // grid exact
    int row = ei[e];
    int col = ei[N_EDGES + e];
    float nr = 0.f;
    if ((unsigned)row < (unsigned)N_NODES && (unsigned)col < (unsigned)N_NODES) {
        nr = g_dinv[row] * w[e] * g_dinv[col];
    } else {
        row = 0; col = 0;                            // safe target, zero weight
    }
    g_erow[e] = row;
    g_ecol[e] = col;
    g_norm[e] = nr;
}

// ---------------- GEMM layer 1: xw = x @ W1   (K=14, bias cancels under BN) ----------------
__global__ void gemm_l1(const float* __restrict__ X, const float* __restrict__ W) {
    __shared__ float Ws[IN_F][HID];
    __shared__ float As[64][IN_F + 1];
    int tid = threadIdx.x;                           // 256
    for (int i = tid; i < IN_F * HID; i += 256) Ws[i / HID][i % HID] = W[i];
    int row0 = blockIdx.x * 64;
    for (int i = tid; i < 64 * IN_F; i += 256) {
        int r = i / IN_F, c = i % IN_F;
        int gr = row0 + r;
        As[r][c] = (gr < N_NODES) ? X[gr * IN_F + c] : 0.f;
    }
    __syncthreads();
    int r  = tid >> 2;
    int cg = (tid & 3) * 16;
    float acc[16];
#pragma unroll
    for (int j = 0; j < 16; j++) acc[j] = 0.f;
#pragma unroll
    for (int k = 0; k < IN_F; k++) {
        float a = As[r][k];
#pragma unroll
        for (int j = 0; j < 16; j++) acc[j] = fmaf(a, Ws[k][cg + j], acc[j]);
    }
    int gr = row0 + r;
    if (gr < N_NODES) {
        float4* out = (float4*)(g_xw + gr * HID + cg);
        out[0] = make_float4(acc[0],  acc[1],  acc[2],  acc[3]);
        out[1] = make_float4(acc[4],  acc[5],  acc[6],  acc[7]);
        out[2] = make_float4(acc[8],  acc[9],  acc[10], acc[11]);
        out[3] = make_float4(acc[12], acc[13], acc[14], acc[15]);
    }
}

// ---------------- GEMM layers 2/3: xw = relu(bn(acc_prev)) @ W   (K=64) ----------------
__global__ void gemm_bn(const float* __restrict__ A, const float* __restrict__ W) {
    __shared__ float Ws[HID][HID];
    __shared__ float As[64][HID + 1];
    __shared__ float sc[HID], sh[HID];
    int tid = threadIdx.x;                           // 256
    for (int i = tid; i < HID * HID; i += 256) Ws[i >> 6][i & 63] = W[i];
    if (tid < HID) { sc[tid] = g_scale[tid]; sh[tid] = g_shift[tid]; }
    __syncthreads();
    int row0 = blockIdx.x * 64;
    for (int i = tid; i < 64 * HID; i += 256) {
        int r = i >> 6, c = i & 63;
        int gr = row0 + r;
        float v = (gr < N_NODES) ? A[gr * HID + c] : 0.f;
        As[r][c] = fmaxf(fmaf(v, sc[c], sh[c]), 0.f);   // fused BN + ReLU
    }
    __syncthreads();
    int r  = tid >> 2;
    int cg = (tid & 3) * 16;
    float acc[16];
#pragma unroll
    for (int j = 0; j < 16; j++) acc[j] = 0.f;
#pragma unroll
    for (int k = 0; k < HID; k++) {
        float a = As[r][k];
#pragma unroll
        for (int j = 0; j < 16; j++) acc[j] = fmaf(a, Ws[k][cg + j], acc[j]);
    }
    int gr = row0 + r;
    if (gr < N_NODES) {
        float4* out = (float4*)(g_xw + gr * HID + cg);
        out[0] = make_float4(acc[0],  acc[1],  acc[2],  acc[3]);
        out[1] = make_float4(acc[4],  acc[5],  acc[6],  acc[7]);
        out[2] = make_float4(acc[8],  acc[9],  acc[10], acc[11]);
        out[3] = make_float4(acc[12], acc[13], acc[14], acc[15]);
    }
}

// ---------------- edge scatter: acc[col] += norm * xw[row]  (16 lanes per edge) ----------------
__global__ void scatter_kernel(float* __restrict__ acc) {
    int t = blockIdx.x * 256 + threadIdx.x;          // grid exact: E*16/256 = 100000 blocks
    int e = t >> 4;
    int c = t & 15;
    int lane = threadIdx.x & 31;
    int src  = lane & ~15;                           // leader of the 16-lane group
    int row = 0, col = 0; float nr = 0.f;
    if ((lane & 15) == 0) {
        row = g_erow[e]; col = g_ecol[e]; nr = g_norm[e];
    }
    row = __shfl_sync(0xffffffffu, row, src);
    col = __shfl_sync(0xffffffffu, col, src);
    nr  = __shfl_sync(0xffffffffu, nr,  src);
    float4 v = ((const float4*)g_xw)[row * 16 + c];
    v.x *= nr; v.y *= nr; v.z *= nr; v.w *= nr;
    red_add4(acc + col * HID + c * 4, v);
}

// ---------------- BN stats + self-loop fold:  acc += dinv2 * xw; accumulate sum/sumsq ----------------
__global__ void stats_kernel(float* __restrict__ acc) {
    int tid = threadIdx.x;
    int c  = tid & 15;
    int rl = tid >> 4;
    int row = blockIdx.x * 16 + rl;
    int stride = gridDim.x * 16;
    float4 s = make_float4(0.f,0.f,0.f,0.f);
    float4 q = make_float4(0.f,0.f,0.f,0.f);
    for (; row < N_NODES; row += stride) {
        float d2 = g_dinv2[row];
        float4 a = ((float4*)acc)[row * 16 + c];
        float4 x = ((const float4*)g_xw)[row * 16 + c];
        a.x = fmaf(d2, x.x, a.x);
        a.y = fmaf(d2, x.y, a.y);
        a.z = fmaf(d2, x.z, a.z);
        a.w = fmaf(d2, x.w, a.w);
        ((float4*)acc)[row * 16 + c] = a;
        s.x += a.x; s.y += a.y; s.z += a.z; s.w += a.w;
        q.x = fmaf(a.x, a.x, q.x);
        q.y = fmaf(a.y, a.y, q.y);
        q.z = fmaf(a.z, a.z, q.z);
        q.w = fmaf(a.w, a.w, q.w);
    }
    __shared__ float ss[128];
    if (tid < 128) ss[tid] = 0.f;
    __syncthreads();
    atomicAdd(&ss[c * 4 + 0], s.x);
    atomicAdd(&ss[c * 4 + 1], s.y);
    atomicAdd(&ss[c * 4 + 2], s.z);
    atomicAdd(&ss[c * 4 + 3], s.w);
    atomicAdd(&ss[64 + c * 4 + 0], q.x);
    atomicAdd(&ss[64 + c * 4 + 1], q.y);
    atomicAdd(&ss[64 + c * 4 + 2], q.z);
    atomicAdd(&ss[64 + c * 4 + 3], q.w);
    __syncthreads();
    if (tid < 128) atomicAdd(&g_stats[tid], ss[tid]);
}

__global__ void finalize_kernel(const float* __restrict__ gamma, const float* __restrict__ beta) {
    int j = threadIdx.x;                             // 64 threads
    const float invN = 1.0f / (float)N_NODES;
    float mean = g_stats[j] * invN;
    float var  = g_stats[64 + j] * invN - mean * mean;
    float inv  = rsqrtf(var + BN_EPS);
    float s = gamma[j] * inv;
    g_scale[j] = s;
    g_shift[j] = beta[j] - mean * s;
}

// ---------------- final: node_embs = relu(bn(acc3)); graph_emb segment-sum (batch sorted, int32) ----------------
__global__ void apply_pool(const float* __restrict__ acc, const int* __restrict__ batch,
                           float* __restrict__ nodes, float* __restrict__ gout) {
    const int R = 32;                                // rows per strip
    int tid = blockIdx.x * blockDim.x + threadIdx.x;
    int c = tid & 15;
    int s = tid >> 4;
    int r0 = s * R;
    if (r0 >= N_NODES) return;
    int r1 = min(r0 + R, N_NODES);
    float4 sc = ((const float4*)g_scale)[c];
    float4 sh = ((const float4*)g_shift)[c];
    float4 sum = make_float4(0.f,0.f,0.f,0.f);
    int curg = batch[r0];
    for (int r = r0; r < r1; r++) {
        int g = batch[r];
        float4 a = ((const float4*)acc)[r * 16 + c];
        float4 t;
        t.x = fmaxf(fmaf(a.x, sc.x, sh.x), 0.f);
        t.y = fmaxf(fmaf(a.y, sc.y, sh.y), 0.f);
        t.z = fmaxf(fmaf(a.z, sc.z, sh.z), 0.f);
        t.w = fmaxf(fmaf(a.w, sc.w, sh.w), 0.f);
        ((float4*)nodes)[r * 16 + c] = t;
        if (g != curg) {                             // flush on graph boundary only
            red_add4(gout + curg * HID + c * 4, sum);
            sum = make_float4(0.f,0.f,0.f,0.f);
            curg = g;
        }
        sum.x += t.x; sum.y += t.y; sum.z += t.z; sum.w += t.w;
    }
    red_add4(gout + curg * HID + c * 4, sum);
}

__global__ void fc_kernel(const float* __restrict__ gout, const float* __restrict__ fcW,
                          const float* __restrict__ fcb, float* __restrict__ out) {
    int tid = blockIdx.x * blockDim.x + threadIdx.x;
    if (tid >= N_GRAPHS * N_CLS) return;
    int g = tid >> 1, cls = tid & 1;
    float s = fcb[cls];
    const float* ge = gout + g * HID;
#pragma unroll
    for (int k = 0; k < HID; k++) s = fmaf(ge[k], fcW[k * 2 + cls], s);
    out[g * 2 + cls] = s;
}

// ---------------- launch ----------------
extern "C" void kernel_launch(void* const* d_in, const int* in_sizes, int n_in,
                              void* d_out, int out_size) {
    const float* x     = (const float*)d_in[0];
    const int*   ei    = (const int*)d_in[1];      // int32 (JAX x64 disabled)
    const int*   batch = (const int*)d_in[2];      // int32
    const float* w     = (const float*)d_in[3];
    const float* W1    = (const float*)d_in[4];
    // d_in[5] = b1 (cancels under BN)
    const float* W2    = (const float*)d_in[6];
    // d_in[7] = b2
    const float* W3    = (const float*)d_in[8];
    // d_in[9] = b3
    const float* g1  = (const float*)d_in[10];
    const float* bt1 = (const float*)d_in[11];
    const float* g2  = (const float*)d_in[12];
    const float* bt2 = (const float*)d_in[13];
    const float* g3  = (const float*)d_in[14];
    const float* bt3 = (const float*)d_in[15];
    const float* fcW = (const float*)d_in[16];
    const float* fcb = (const float*)d_in[17];

    float *accA, *accB, *dinvp, *statsp;
    cudaGetSymbolAddress((void**)&accA,  g_accA);
    cudaGetSymbolAddress((void**)&accB,  g_accB);
    cudaGetSymbolAddress((void**)&dinvp, g_dinv);
    cudaGetSymbolAddress((void**)&statsp, g_stats);

    float* out   = (float*)d_out;                        // [2048, 2]
    float* nodes = out + N_GRAPHS * N_CLS;               // [100000, 64]
    float* gout  = nodes + (size_t)N_NODES * HID;        // [2048, 64]

    const int EB = N_EDGES / 256;        // 6250
    const int SB = (N_EDGES * 16) / 256; // 100000
    const int GB = (N_NODES + 63) / 64;  // 1563
    const int ACC4 = N_NODES * HID / 4;

    // ---- edge prep ----
    zero4<<<256, 256>>>((float4*)dinvp, N_NODES / 4);
    deg_kernel<<<EB, 256>>>(ei, w);
    dinv_kernel<<<(N_NODES + 255) / 256, 256>>>();
    prep_kernel<<<EB, 256>>>(ei, w);

    // ---- layer 1 ----
    zero4<<<2048, 256>>>((float4*)accA, ACC4);
    gemm_l1<<<GB, 256>>>(x, W1);
    scatter_kernel<<<SB, 256>>>(accA);
    zero4<<<1, 32>>>((float4*)statsp, 32);
    stats_kernel<<<1024, 256>>>(accA);
    finalize_kernel<<<1, 64>>>(g1, bt1);

    // ---- layer 2 ----
    zero4<<<2048, 256>>>((float4*)accB, ACC4);
    gemm_bn<<<GB, 256>>>(accA, W2);
    scatter_kernel<<<SB, 256>>>(accB);
    zero4<<<1, 32>>>((float4*)statsp, 32);
    stats_kernel<<<1024, 256>>>(accB);
    finalize_kernel<<<1, 64>>>(g2, bt2);

    // ---- layer 3 ----
    zero4<<<2048, 256>>>((float4*)accA, ACC4);
    gemm_bn<<<GB, 256>>>(accB, W3);
    scatter_kernel<<<SB, 256>>>(accA);
    zero4<<<1, 32>>>((float4*)statsp, 32);
    stats_kernel<<<1024, 256>>>(accA);
    finalize_kernel<<<1, 64>>>(g3, bt3);

    // ---- pool + fc ----
    zero4<<<128, 256>>>((float4*)gout, N_GRAPHS * HID / 4);
    {
        int strips = (N_NODES + 31) / 32;                // 3125
        int threads = strips * 16;                       // 50000
        apply_pool<<<(threads + 255) / 256, 256>>>(accA, batch, nodes, gout);
    }
    fc_kernel<<<16, 256>>>(gout, fcW, fcb, out);
}

// round 15
// speedup vs baseline: 1.0528x; 1.0528x over previous
#include <cuda_runtime.h>
#include <cuda_bf16.h>

#define N_NODES  100000
#define N_EDGES  1600000
#define N_GRAPHS 2048
#define HID      64
#define IN_F     14
#define N_CLS    2
#define BN_EPS   1e-5f

// ---------------- scratch (static __device__: allocation-free) ----------------
__device__ float g_dinv [N_NODES];          // deg accum -> dinv
__device__ float g_dinv2[N_NODES];          // 1/deg  (self-loop coeff)
__device__ int   g_erow [N_EDGES];
__device__ int   g_ecol [N_EDGES];
__device__ float g_norm [N_EDGES];
__device__ float g_xw   [N_NODES * HID];    // x @ W  (gather source)
__device__ float g_accA [N_NODES * HID];    // ping
__device__ float g_accB [N_NODES * HID];    // pong
__device__ float g_stats[128];              // [0:64) sum, [64:128) sumsq
__device__ float g_scale[HID];
__device__ float g_shift[HID];

// ---------------- helpers ----------------
__device__ __forceinline__ void red_add4(float* p, float4 v) {
    asm volatile("red.global.add.v4.f32 [%0], {%1,%2,%3,%4};"
                 :: "l"(p), "f"(v.x), "f"(v.y), "f"(v.z), "f"(v.w) : "memory");
}

__global__ void zero4(float4* __restrict__ p, int n4) {
    int i = blockIdx.x * blockDim.x + threadIdx.x;
    int stride = gridDim.x * blockDim.x;
    float4 z = make_float4(0.f, 0.f, 0.f, 0.f);
    for (; i < n4; i += stride) p[i] = z;
}

// ---------------- edge prep (indices are int32) ----------------
__global__ void deg_kernel(const int* __restrict__ ei, const float* __restrict__ w) {
    int e = blockIdx.x * blockDim.x + threadIdx.x;   // grid exact: 1.6M/256
    int col = ei[N_EDGES + e];
    if ((unsigned)col < (unsigned)N_NODES)
        atomicAdd(&g_dinv[col], w[e]);
}

__global__ void dinv_kernel() {
    int i = blockIdx.x * blockDim.x + threadIdx.x;
    if (i >= N_NODES) return;
    float d = g_dinv[i] + 1.0f;                      // +1 self loop
    g_dinv[i]  = rsqrtf(d);
    g_dinv2[i] = 1.0f / d;
}

__global__ void prep_kernel(const int* __restrict__ ei, const float* __restrict__ w) {
    int e = blockIdx.x * blockDim.x + threadIdx.x;   // grid exact
    int row = ei[e];
    int col = ei[N_EDGES + e];
    float nr = 0.f;
    if ((unsigned)row < (unsigned)N_NODES && (unsigned)col < (unsigned)N_NODES) {
        nr = g_dinv[row] * w[e] * g_dinv[col];
    } else {
        row = 0; col = 0;                            // safe target, zero weight
    }
    g_erow[e] = row;
    g_ecol[e] = col;
    g_norm[e] = nr;
}

// ---------------- GEMM layer 1: xw = x @ W1; acc = dinv2 * xw  (self-loop fused) ----------------
__global__ void __launch_bounds__(256) gemm_l1(const float* __restrict__ X, const float* __restrict__ W,
                                               float* __restrict__ accout) {
    __shared__ float Ws[IN_F][HID];
    __shared__ float As[64][IN_F + 1];
    int tid = threadIdx.x;                           // 256
    for (int i = tid; i < IN_F * HID; i += 256) Ws[i / HID][i % HID] = W[i];
    int row0 = blockIdx.x * 64;
    for (int i = tid; i < 64 * IN_F; i += 256) {
        int r = i / IN_F, c = i % IN_F;
        int gr = row0 + r;
        As[r][c] = (gr < N_NODES) ? X[gr * IN_F + c] : 0.f;
    }
    __syncthreads();
    int r  = tid >> 2;
    int cg = (tid & 3) * 16;
    float acc[16];
#pragma unroll
    for (int j = 0; j < 16; j++) acc[j] = 0.f;
#pragma unroll
    for (int k = 0; k < IN_F; k++) {
        float a = As[r][k];
#pragma unroll
        for (int j = 0; j < 16; j++) acc[j] = fmaf(a, Ws[k][cg + j], acc[j]);
    }
    int gr = row0 + r;
    if (gr < N_NODES) {
        float d2 = g_dinv2[gr];
        float4* out = (float4*)(g_xw + gr * HID + cg);
        float4* ao  = (float4*)(accout + gr * HID + cg);
        out[0] = make_float4(acc[0],  acc[1],  acc[2],  acc[3]);
        out[1] = make_float4(acc[4],  acc[5],  acc[6],  acc[7]);
        out[2] = make_float4(acc[8],  acc[9],  acc[10], acc[11]);
        out[3] = make_float4(acc[12], acc[13], acc[14], acc[15]);
        ao[0] = make_float4(d2*acc[0],  d2*acc[1],  d2*acc[2],  d2*acc[3]);
        ao[1] = make_float4(d2*acc[4],  d2*acc[5],  d2*acc[6],  d2*acc[7]);
        ao[2] = make_float4(d2*acc[8],  d2*acc[9],  d2*acc[10], d2*acc[11]);
        ao[3] = make_float4(d2*acc[12], d2*acc[13], d2*acc[14], d2*acc[15]);
    }
}

// ---------------- GEMM layers 2/3: xw = relu(bn(acc_prev)) @ W; acc = dinv2 * xw ----------------
__global__ void __launch_bounds__(256) gemm_bn(const float* __restrict__ A, const float* __restrict__ W,
                                               float* __restrict__ accout) {
    __shared__ float Ws[HID][HID];
    __shared__ float As[64][HID + 1];
    __shared__ float sc[HID], sh[HID];
    int tid = threadIdx.x;                           // 256
    for (int i = tid; i < HID * HID; i += 256) Ws[i >> 6][i & 63] = W[i];
    if (tid < HID) { sc[tid] = g_scale[tid]; sh[tid] = g_shift[tid]; }
    __syncthreads();
    int row0 = blockIdx.x * 64;
    for (int i = tid; i < 64 * HID; i += 256) {
        int r = i >> 6, c = i & 63;
        int gr = row0 + r;
        float v = (gr < N_NODES) ? A[gr * HID + c] : 0.f;
        As[r][c] = fmaxf(fmaf(v, sc[c], sh[c]), 0.f);   // fused BN + ReLU
    }
    __syncthreads();
    int r  = tid >> 2;
    int cg = (tid & 3) * 16;
    float acc[16];
#pragma unroll
    for (int j = 0; j < 16; j++) acc[j] = 0.f;
#pragma unroll
    for (int k = 0; k < HID; k++) {
        float a = As[r][k];
#pragma unroll
        for (int j = 0; j < 16; j++) acc[j] = fmaf(a, Ws[k][cg + j], acc[j]);
    }
    int gr = row0 + r;
    if (gr < N_NODES) {
        float d2 = g_dinv2[gr];
        float4* out = (float4*)(g_xw + gr * HID + cg);
        float4* ao  = (float4*)(accout + gr * HID + cg);
        out[0] = make_float4(acc[0],  acc[1],  acc[2],  acc[3]);
        out[1] = make_float4(acc[4],  acc[5],  acc[6],  acc[7]);
        out[2] = make_float4(acc[8],  acc[9],  acc[10], acc[11]);
        out[3] = make_float4(acc[12], acc[13], acc[14], acc[15]);
        ao[0] = make_float4(d2*acc[0],  d2*acc[1],  d2*acc[2],  d2*acc[3]);
        ao[1] = make_float4(d2*acc[4],  d2*acc[5],  d2*acc[6],  d2*acc[7]);
        ao[2] = make_float4(d2*acc[8],  d2*acc[9],  d2*acc[10], d2*acc[11]);
        ao[3] = make_float4(d2*acc[12], d2*acc[13], d2*acc[14], d2*acc[15]);
    }
}

// ---------------- edge scatter: acc[col] += norm * xw[row]  (16 lanes per edge) ----------------
// IDENTICAL to the round-7 passing version: full-warp shfl, uniform control flow, no loops.
__global__ void scatter_kernel(float* __restrict__ acc) {
    int t = blockIdx.x * 256 + threadIdx.x;          // grid exact: E*16/256 = 100000 blocks
    int e = t >> 4;
    int c = t & 15;
    int lane = threadIdx.x & 31;
    int src  = lane & ~15;                           // leader of the 16-lane group
    int row = 0, col = 0; float nr = 0.f;
    if ((lane & 15) == 0) {
        row = g_erow[e]; col = g_ecol[e]; nr = g_norm[e];
    }
    row = __shfl_sync(0xffffffffu, row, src);
    col = __shfl_sync(0xffffffffu, col, src);
    nr  = __shfl_sync(0xffffffffu, nr,  src);
    float4 v = ((const float4*)g_xw)[row * 16 + c];
    v.x *= nr; v.y *= nr; v.z *= nr; v.w *= nr;
    red_add4(acc + col * HID + c * 4, v);
}

// ---------------- BN stats (read-only): accumulate sum/sumsq of final acc ----------------
__global__ void stats_kernel(const float* __restrict__ acc) {
    int tid = threadIdx.x;
    int c  = tid & 15;
    int rl = tid >> 4;
    int row = blockIdx.x * 16 + rl;
    int stride = gridDim.x * 16;
    float4 s = make_float4(0.f,0.f,0.f,0.f);
    float4 q = make_float4(0.f,0.f,0.f,0.f);
    for (; row < N_NODES; row += stride) {
        float4 a = ((const float4*)acc)[row * 16 + c];
        s.x += a.x; s.y += a.y; s.z += a.z; s.w += a.w;
        q.x = fmaf(a.x, a.x, q.x);
        q.y = fmaf(a.y, a.y, q.y);
        q.z = fmaf(a.z, a.z, q.z);
        q.w = fmaf(a.w, a.w, q.w);
    }
    __shared__ float ss[128];
    if (tid < 128) ss[tid] = 0.f;
    __syncthreads();
    atomicAdd(&ss[c * 4 + 0], s.x);
    atomicAdd(&ss[c * 4 + 1], s.y);
    atomicAdd(&ss[c * 4 + 2], s.z);
    atomicAdd(&ss[c * 4 + 3], s.w);
    atomicAdd(&ss[64 + c * 4 + 0], q.x);
    atomicAdd(&ss[64 + c * 4 + 1], q.y);
    atomicAdd(&ss[64 + c * 4 + 2], q.z);
    atomicAdd(&ss[64 + c * 4 + 3], q.w);
    __syncthreads();
    if (tid < 128) atomicAdd(&g_stats[tid], ss[tid]);
}

__global__ void finalize_kernel(const float* __restrict__ gamma, const float* __restrict__ beta) {
    int j = threadIdx.x;                             // 64 threads
    const float invN = 1.0f / (float)N_NODES;
    float mean = g_stats[j] * invN;
    float var  = g_stats[64 + j] * invN - mean * mean;
    float inv  = rsqrtf(var + BN_EPS);
    float s = gamma[j] * inv;
    g_scale[j] = s;
    g_shift[j] = beta[j] - mean * s;
}

// ---------------- final: node_embs = relu(bn(acc3)); graph_emb segment-sum (batch sorted) ----------------
__global__ void apply_pool(const float* __restrict__ acc, const int* __restrict__ batch,
                           float* __restrict__ nodes, float* __restrict__ gout) {
    const int R = 32;
    int tid = blockIdx.x * blockDim.x + threadIdx.x;
    int c = tid & 15;
    int s = tid >> 4;
    int r0 = s * R;
    if (r0 >= N_NODES) return;
    int r1 = min(r0 + R, N_NODES);
    float4 sc = ((const float4*)g_scale)[c];
    float4 sh = ((const float4*)g_shift)[c];
    float4 sum = make_float4(0.f,0.f,0.f,0.f);
    int curg = batch[r0];
    for (int r = r0; r < r1; r++) {
        int g = batch[r];
        float4 a = ((const float4*)acc)[r * 16 + c];
        float4 t;
        t.x = fmaxf(fmaf(a.x, sc.x, sh.x), 0.f);
        t.y = fmaxf(fmaf(a.y, sc.y, sh.y), 0.f);
        t.z = fmaxf(fmaf(a.z, sc.z, sh.z), 0.f);
        t.w = fmaxf(fmaf(a.w, sc.w, sh.w), 0.f);
        ((float4*)nodes)[r * 16 + c] = t;
        if (g != curg) {
            red_add4(gout + curg * HID + c * 4, sum);
            sum = make_float4(0.f,0.f,0.f,0.f);
            curg = g;
        }
        sum.x += t.x; sum.y += t.y; sum.z += t.z; sum.w += t.w;
    }
    red_add4(gout + curg * HID + c * 4, sum);
}

__global__ void fc_kernel(const float* __restrict__ gout, const float* __restrict__ fcW,
                          const float* __restrict__ fcb, float* __restrict__ out) {
    int tid = blockIdx.x * blockDim.x + threadIdx.x;
    if (tid >= N_GRAPHS * N_CLS) return;
    int g = tid >> 1, cls = tid & 1;
    float s = fcb[cls];
    const float* ge = gout + g * HID;
#pragma unroll
    for (int k = 0; k < HID; k++) s = fmaf(ge[k], fcW[k * 2 + cls], s);
    out[g * 2 + cls] = s;
}

// ---------------- launch ----------------
extern "C" void kernel_launch(void* const* d_in, const int* in_sizes, int n_in,
                              void* d_out, int out_size) {
    const float* x     = (const float*)d_in[0];
    const int*   ei    = (const int*)d_in[1];      // int32 (JAX x64 disabled)
    const int*   batch = (const int*)d_in[2];      // int32
    const float* w     = (const float*)d_in[3];
    const float* W1    = (const float*)d_in[4];
    const float* W2    = (const float*)d_in[6];
    const float* W3    = (const float*)d_in[8];
    const float* g1  = (const float*)d_in[10];
    const float* bt1 = (const float*)d_in[11];
    const float* g2  = (const float*)d_in[12];
    const float* bt2 = (const float*)d_in[13];
    const float* g3  = (const float*)d_in[14];
    const float* bt3 = (const float*)d_in[15];
    const float* fcW = (const float*)d_in[16];
    const float* fcb = (const float*)d_in[17];

    float *accA, *accB, *dinvp, *statsp;
    cudaGetSymbolAddress((void**)&accA,  g_accA);
    cudaGetSymbolAddress((void**)&accB,  g_accB);
    cudaGetSymbolAddress((void**)&dinvp, g_dinv);
    cudaGetSymbolAddress((void**)&statsp, g_stats);

    float* out   = (float*)d_out;                        // [2048, 2]
    float* nodes = out + N_GRAPHS * N_CLS;               // [100000, 64]
    float* gout  = nodes + (size_t)N_NODES * HID;        // [2048, 64]

    const int EB = N_EDGES / 256;        // 6250 (grid exact)
    const int SB = (N_EDGES * 16) / 256; // 100000 (grid exact)
    const int GB = (N_NODES + 63) / 64;  // 1563

    // ---- edge prep ----
    zero4<<<256, 256>>>((float4*)dinvp, N_NODES / 4);
    deg_kernel<<<EB, 256>>>(ei, w);
    dinv_kernel<<<(N_NODES + 255) / 256, 256>>>();
    prep_kernel<<<EB, 256>>>(ei, w);

    // ---- layer 1 ----
    gemm_l1<<<GB, 256>>>(x, W1, accA);               // writes xw and acc=d2*xw
    scatter_kernel<<<SB, 256>>>(accA);
    zero4<<<1, 32>>>((float4*)statsp, 32);
    stats_kernel<<<1024, 256>>>(accA);
    finalize_kernel<<<1, 64>>>(g1, bt1);

    // ---- layer 2 ----
    gemm_bn<<<GB, 256>>>(accA, W2, accB);
    scatter_kernel<<<SB, 256>>>(accB);
    zero4<<<1, 32>>>((float4*)statsp, 32);
    stats_kernel<<<1024, 256>>>(accB);
    finalize_kernel<<<1, 64>>>(g2, bt2);

    // ---- layer 3 ----
    gemm_bn<<<GB, 256>>>(accB, W3, accA);
    scatter_kernel<<<SB, 256>>>(accA);
    zero4<<<1, 32>>>((float4*)statsp, 32);
    stats_kernel<<<1024, 256>>>(accA);
    finalize_kernel<<<1, 64>>>(g3, bt3);

    // ---- pool + fc ----
    zero4<<<128, 256>>>((float4*)gout, N_GRAPHS * HID / 4);
    {
        int strips = (N_NODES + 31) / 32;                // 3125
        int threads = strips * 16;                       // 50000
        apply_pool<<<(threads + 255) / 256, 256>>>(accA, batch, nodes, gout);
    }
    fc_kernel<<<16, 256>>>(gout, fcW, fcb, out);
}